// round 1
// baseline (speedup 1.0000x reference)
#include <cuda_runtime.h>
#include <math.h>

#define ALPHA 0.2f
#define NEG_BIG -9000000000000000.0f

constexpr int Bb   = 32;
constexpr int Nn   = 1024;
constexpr int Fin  = 512;
constexpr int Hh   = 512;
constexpr int ROWS = Bb * Nn;   // 32768

// Scratch (no cudaMalloc allowed)
__device__ float g_v1[Hh];
__device__ float g_v2[Hh];
__device__ float g_f1[ROWS];
__device__ float g_f2[ROWS];

// ---------------------------------------------------------------------------
// Kernel A: v1 = w @ a[:H], v2 = w @ a[H:]. One block per output element f.
// w is (F_IN, H) row-major, so v[f] = dot(w[f,:], a_half).
// ---------------------------------------------------------------------------
__global__ void k_wa(const float* __restrict__ w, const float* __restrict__ a)
{
    int f = blockIdx.x;
    float s1 = 0.f, s2 = 0.f;
    for (int h = threadIdx.x; h < Hh; h += blockDim.x) {
        float wv = w[f * Hh + h];
        s1 = fmaf(wv, a[h],      s1);
        s2 = fmaf(wv, a[Hh + h], s2);
    }
    #pragma unroll
    for (int o = 16; o > 0; o >>= 1) {
        s1 += __shfl_xor_sync(0xffffffffu, s1, o);
        s2 += __shfl_xor_sync(0xffffffffu, s2, o);
    }
    __shared__ float sm1[8], sm2[8];
    int wid = threadIdx.x >> 5, lane = threadIdx.x & 31;
    if (lane == 0) { sm1[wid] = s1; sm2[wid] = s2; }
    __syncthreads();
    if (threadIdx.x == 0) {
        float t1 = 0.f, t2 = 0.f;
        #pragma unroll
        for (int k = 0; k < 8; k++) { t1 += sm1[k]; t2 += sm2[k]; }
        g_v1[f] = t1;
        g_v2[f] = t2;
    }
}

// ---------------------------------------------------------------------------
// Kernel B: f1[row] = context[row,:] . v1 ; f2[row] = context[row,:] . v2
// One warp per row (row = b*N + n), 8 warps per block.
// ---------------------------------------------------------------------------
__global__ void k_f(const float* __restrict__ ctx)
{
    __shared__ float sv1[Hh], sv2[Hh];
    for (int t = threadIdx.x; t < Hh; t += blockDim.x) {
        sv1[t] = g_v1[t];
        sv2[t] = g_v2[t];
    }
    __syncthreads();

    int wid  = threadIdx.x >> 5;
    int lane = threadIdx.x & 31;
    int row  = blockIdx.x * 8 + wid;

    const float4* crow = (const float4*)(ctx + (size_t)row * Fin);
    float s1 = 0.f, s2 = 0.f;
    #pragma unroll
    for (int k = 0; k < 4; k++) {
        int idx = lane + k * 32;        // float4 index within row, 0..127
        float4 c = crow[idx];
        int h = idx * 4;
        s1 = fmaf(c.x, sv1[h], s1); s1 = fmaf(c.y, sv1[h+1], s1);
        s1 = fmaf(c.z, sv1[h+2], s1); s1 = fmaf(c.w, sv1[h+3], s1);
        s2 = fmaf(c.x, sv2[h], s2); s2 = fmaf(c.y, sv2[h+1], s2);
        s2 = fmaf(c.z, sv2[h+2], s2); s2 = fmaf(c.w, sv2[h+3], s2);
    }
    #pragma unroll
    for (int o = 16; o > 0; o >>= 1) {
        s1 += __shfl_xor_sync(0xffffffffu, s1, o);
        s2 += __shfl_xor_sync(0xffffffffu, s2, o);
    }
    if (lane == 0) { g_f1[row] = s1; g_f2[row] = s2; }
}

// ---------------------------------------------------------------------------
// Kernel C: one block per (b,i) row. 256 threads x 4 j's each.
//   e[j]   = leaky_relu(f1[b,i] + f2[b,j]); masked -> NEG_BIG
//   att    = softmax_j(e); out = softplus(att)
// Masked entries keep the literal NEG_BIG so degenerate (all-masked) rows
// reproduce the reference exactly (exp(0)/N path).
// ---------------------------------------------------------------------------
__global__ void k_att(const int* __restrict__ adj, float* __restrict__ out)
{
    int row = blockIdx.x;          // b*N + i
    int b   = row >> 10;
    int tid = threadIdx.x;
    int wid  = tid >> 5;
    int lane = tid & 31;

    const int4   a4  = ((const int4*)  (adj  + (size_t)row * Nn))[tid];
    const float4 f2v = ((const float4*)(g_f2 + ((size_t)b << 10)))[tid];
    const float  f1i = g_f1[row];

    float e0 = f1i + f2v.x; e0 = (e0 > 0.f) ? e0 : ALPHA * e0; e0 = (a4.x > 0) ? e0 : NEG_BIG;
    float e1 = f1i + f2v.y; e1 = (e1 > 0.f) ? e1 : ALPHA * e1; e1 = (a4.y > 0) ? e1 : NEG_BIG;
    float e2 = f1i + f2v.z; e2 = (e2 > 0.f) ? e2 : ALPHA * e2; e2 = (a4.z > 0) ? e2 : NEG_BIG;
    float e3 = f1i + f2v.w; e3 = (e3 > 0.f) ? e3 : ALPHA * e3; e3 = (a4.w > 0) ? e3 : NEG_BIG;

    __shared__ float sred[8];
    __shared__ float sbc_m, sbc_s;

    // --- block max ---
    float m = fmaxf(fmaxf(e0, e1), fmaxf(e2, e3));
    #pragma unroll
    for (int o = 16; o > 0; o >>= 1)
        m = fmaxf(m, __shfl_xor_sync(0xffffffffu, m, o));
    if (lane == 0) sred[wid] = m;
    __syncthreads();
    if (tid == 0) {
        float mm = sred[0];
        #pragma unroll
        for (int k = 1; k < 8; k++) mm = fmaxf(mm, sred[k]);
        sbc_m = mm;
    }
    __syncthreads();
    const float M = sbc_m;

    // --- exp & block sum ---
    float p0 = expf(e0 - M);
    float p1 = expf(e1 - M);
    float p2 = expf(e2 - M);
    float p3 = expf(e3 - M);
    float s = (p0 + p1) + (p2 + p3);
    #pragma unroll
    for (int o = 16; o > 0; o >>= 1)
        s += __shfl_xor_sync(0xffffffffu, s, o);
    __syncthreads();              // protect sred reuse
    if (lane == 0) sred[wid] = s;
    __syncthreads();
    if (tid == 0) {
        float ss = 0.f;
        #pragma unroll
        for (int k = 0; k < 8; k++) ss += sred[k];
        sbc_s = ss;
    }
    __syncthreads();
    const float inv = 1.0f / sbc_s;

    // --- softplus(att) and store ---
    float4 r;
    r.x = log1pf(expf(p0 * inv) - 1.0f + 1.0f - 1.0f);  // placeholder avoided below
    // (computed properly:)
    r.x = log1pf(expf(p0 * inv));
    r.y = log1pf(expf(p1 * inv));
    r.z = log1pf(expf(p2 * inv));
    r.w = log1pf(expf(p3 * inv));
    ((float4*)(out + (size_t)row * Nn))[tid] = r;
}

extern "C" void kernel_launch(void* const* d_in, const int* in_sizes, int n_in,
                              void* d_out, int out_size)
{
    const float* ctx = (const float*)d_in[0];   // (B, N, F_IN) fp32
    const int*   adj = (const int*)  d_in[1];   // (B, N, N) int32
    const float* w   = (const float*)d_in[2];   // (F_IN, H) fp32
    const float* a   = (const float*)d_in[3];   // (2H, 1) fp32
    float* out = (float*)d_out;

    k_wa <<<Fin,       256>>>(w, a);
    k_f  <<<ROWS / 8,  256>>>(ctx);
    k_att<<<ROWS,      256>>>(adj, out);
}

// round 14
// speedup vs baseline: 1.5582x; 1.5582x over previous
#include <cuda_runtime.h>
#include <math.h>

#define ALPHA 0.2f
#define NEG_BIG -9000000000000000.0f

constexpr int Bb   = 32;
constexpr int Nn   = 1024;
constexpr int Fin  = 512;
constexpr int Hh   = 512;
constexpr int ROWS = Bb * Nn;   // 32768

// Scratch (no cudaMalloc allowed)
__device__ float g_v1[Hh];
__device__ float g_v2[Hh];
__device__ float g_f1[ROWS];
__device__ float g_f2[ROWS];

// ---------------------------------------------------------------------------
// Kernel A: v1[f] = dot(w[f,:], a[:H]);  v2[f] = dot(w[f,:], a[H:])
// Warp per f, 8 warps/block, 64 blocks. Shuffle-only reduction.
// ---------------------------------------------------------------------------
__global__ void __launch_bounds__(256) k_wa(const float* __restrict__ w,
                                            const float* __restrict__ a)
{
    int lane = threadIdx.x & 31;
    int wid  = threadIdx.x >> 5;
    int f    = blockIdx.x * 8 + wid;

    const float4* wr = (const float4*)(w + (size_t)f * Hh);
    const float4* a1 = (const float4*)a;
    const float4* a2 = (const float4*)(a + Hh);

    float s1 = 0.f, s2 = 0.f;
    #pragma unroll
    for (int k = 0; k < 4; k++) {
        int idx = lane + k * 32;          // 0..127 float4 within the row
        float4 wv = wr[idx];
        float4 x  = __ldg(&a1[idx]);
        float4 y  = __ldg(&a2[idx]);
        s1 = fmaf(wv.x, x.x, s1); s1 = fmaf(wv.y, x.y, s1);
        s1 = fmaf(wv.z, x.z, s1); s1 = fmaf(wv.w, x.w, s1);
        s2 = fmaf(wv.x, y.x, s2); s2 = fmaf(wv.y, y.y, s2);
        s2 = fmaf(wv.z, y.z, s2); s2 = fmaf(wv.w, y.w, s2);
    }
    #pragma unroll
    for (int o = 16; o > 0; o >>= 1) {
        s1 += __shfl_xor_sync(0xffffffffu, s1, o);
        s2 += __shfl_xor_sync(0xffffffffu, s2, o);
    }
    if (lane == 0) { g_v1[f] = s1; g_v2[f] = s2; }
}

// ---------------------------------------------------------------------------
// Kernel B: f1[row] = context[row,:] . v1 ; f2[row] = context[row,:] . v2
// One warp per row, 8 warps per block, shuffle-only reduction.
// ---------------------------------------------------------------------------
__global__ void __launch_bounds__(256) k_f(const float* __restrict__ ctx)
{
    __shared__ float sv1[Hh], sv2[Hh];
    for (int t = threadIdx.x; t < Hh; t += blockDim.x) {
        sv1[t] = g_v1[t];
        sv2[t] = g_v2[t];
    }
    __syncthreads();

    int wid  = threadIdx.x >> 5;
    int lane = threadIdx.x & 31;
    int row  = blockIdx.x * 8 + wid;

    const float4* crow = (const float4*)(ctx + (size_t)row * Fin);
    float s1 = 0.f, s2 = 0.f;
    #pragma unroll
    for (int k = 0; k < 4; k++) {
        int idx = lane + k * 32;
        float4 c = crow[idx];
        int h = idx * 4;
        s1 = fmaf(c.x, sv1[h],   s1); s1 = fmaf(c.y, sv1[h+1], s1);
        s1 = fmaf(c.z, sv1[h+2], s1); s1 = fmaf(c.w, sv1[h+3], s1);
        s2 = fmaf(c.x, sv2[h],   s2); s2 = fmaf(c.y, sv2[h+1], s2);
        s2 = fmaf(c.z, sv2[h+2], s2); s2 = fmaf(c.w, sv2[h+3], s2);
    }
    #pragma unroll
    for (int o = 16; o > 0; o >>= 1) {
        s1 += __shfl_xor_sync(0xffffffffu, s1, o);
        s2 += __shfl_xor_sync(0xffffffffu, s2, o);
    }
    if (lane == 0) { g_f1[row] = s1; g_f2[row] = s2; }
}

// ---------------------------------------------------------------------------
// Kernel C: warp per (b,i) row. 8 rows/block, grid = ROWS/8 = 4096.
// Each lane owns 32 j's (8 x float4). All reductions are warp shuffles;
// no shared memory, no __syncthreads.
//   e = leaky_relu(f1[b,i] + f2[b,j]); masked -> NEG_BIG (literal, so
//   all-masked rows reproduce reference's exp(0)/N degenerate path)
//   att = softmax_j(e); out = softplus(att) = log(1 + exp(att))
// ---------------------------------------------------------------------------
__global__ void __launch_bounds__(256) k_att(const int* __restrict__ adj,
                                             float* __restrict__ out)
{
    int wid  = threadIdx.x >> 5;
    int lane = threadIdx.x & 31;
    int row  = blockIdx.x * 8 + wid;     // b*N + i
    int b    = row >> 10;

    const int4*   arow = (const int4*)  (adj  + (size_t)row * Nn);
    const float4* f2r  = (const float4*)(g_f2 + ((size_t)b << 10));
    const float   f1i  = g_f1[row];

    float4 e[8];
    #pragma unroll
    for (int k = 0; k < 8; k++) {
        int idx   = lane + k * 32;       // float4 index 0..255
        int4   a4 = arow[idx];
        float4 fv = f2r[idx];
        float t;
        t = f1i + fv.x; t = (t > 0.f) ? t : ALPHA * t; e[k].x = (a4.x > 0) ? t : NEG_BIG;
        t = f1i + fv.y; t = (t > 0.f) ? t : ALPHA * t; e[k].y = (a4.y > 0) ? t : NEG_BIG;
        t = f1i + fv.z; t = (t > 0.f) ? t : ALPHA * t; e[k].z = (a4.z > 0) ? t : NEG_BIG;
        t = f1i + fv.w; t = (t > 0.f) ? t : ALPHA * t; e[k].w = (a4.w > 0) ? t : NEG_BIG;
    }

    // --- warp max ---
    float m = -INFINITY;
    #pragma unroll
    for (int k = 0; k < 8; k++) {
        m = fmaxf(m, fmaxf(fmaxf(e[k].x, e[k].y), fmaxf(e[k].z, e[k].w)));
    }
    #pragma unroll
    for (int o = 16; o > 0; o >>= 1)
        m = fmaxf(m, __shfl_xor_sync(0xffffffffu, m, o));

    // --- exp (in place) & warp sum ---
    float s = 0.f;
    #pragma unroll
    for (int k = 0; k < 8; k++) {
        e[k].x = __expf(e[k].x - m);
        e[k].y = __expf(e[k].y - m);
        e[k].z = __expf(e[k].z - m);
        e[k].w = __expf(e[k].w - m);
        s += (e[k].x + e[k].y) + (e[k].z + e[k].w);
    }
    #pragma unroll
    for (int o = 16; o > 0; o >>= 1)
        s += __shfl_xor_sync(0xffffffffu, s, o);
    const float inv = 1.0f / s;

    // --- softplus(att) and store ---
    float4* orow = (float4*)(out + (size_t)row * Nn);
    #pragma unroll
    for (int k = 0; k < 8; k++) {
        float4 r;
        r.x = __logf(1.0f + __expf(e[k].x * inv));
        r.y = __logf(1.0f + __expf(e[k].y * inv));
        r.z = __logf(1.0f + __expf(e[k].z * inv));
        r.w = __logf(1.0f + __expf(e[k].w * inv));
        orow[lane + k * 32] = r;
    }
}

extern "C" void kernel_launch(void* const* d_in, const int* in_sizes, int n_in,
                              void* d_out, int out_size)
{
    const float* ctx = (const float*)d_in[0];   // (B, N, F_IN) fp32
    const int*   adj = (const int*)  d_in[1];   // (B, N, N) int32
    const float* w   = (const float*)d_in[2];   // (F_IN, H) fp32
    const float* a   = (const float*)d_in[3];   // (2H, 1) fp32
    float* out = (float*)d_out;

    k_wa <<<Fin / 8,  256>>>(w, a);
    k_f  <<<ROWS / 8, 256>>>(ctx);
    k_att<<<ROWS / 8, 256>>>(adj, out);
}